// round 2
// baseline (speedup 1.0000x reference)
#include <cuda_runtime.h>
#include <cuda_bf16.h>
#include <cstdint>

// Causal attention, B=16, N=2048, D=256, fp32 I/O.
// FlashAttention-2 style, tf32 mma.sync (m16n8k8), fragment-permuted smem layouts.

#define BQ    128              // q-tile rows per block
#define BK    32               // k-tile rows per iteration
#define NWARP 8
#define NTHR  256
#define BATCH 16
#define SEQ   2048
#define DIM   256
#define NTQ   (SEQ / BQ)       // 16 q-tiles per batch
#define QK_SCALE 0.0625f       // 1/sqrt(256)
#define LOG2E 1.4426950408889634f

// smem (uint32 words): tf32 bit patterns
//  Qs: [BQ/16=8][32 d-chunks][32 lanes][4]  = 32768
//  Ks: [BK/8=4][32 d-chunks][32 lanes][2]   =  8192
//  Vs: [DIM/8=32][BK/8=4][32 lanes][2]      =  8192
//  Ps: [8 warps][4 k-chunks][32 lanes][4]   =  4096
//  pads: 32 ints
#define QS_OFF 0
#define KS_OFF 32768
#define VS_OFF 40960
#define PS_OFF 49152
#define PAD_OFF 53248
#define SMEM_WORDS (53248 + 32)
#define SMEM_BYTES (SMEM_WORDS * 4)

__device__ __forceinline__ uint32_t f2tf32(float x) {
    uint32_t u;
    asm("cvt.rna.tf32.f32 %0, %1;" : "=r"(u) : "f"(x));
    return u;
}

__device__ __forceinline__ float ex2(float x) {
    float r;
    asm("ex2.approx.ftz.f32 %0, %1;" : "=f"(r) : "f"(x));
    return r;
}

__device__ __forceinline__ void mma8(float* d, const uint32_t* a, const uint32_t* b) {
    asm volatile(
        "mma.sync.aligned.m16n8k8.row.col.f32.tf32.tf32.f32 "
        "{%0,%1,%2,%3},{%4,%5,%6,%7},{%8,%9},{%0,%1,%2,%3};\n"
        : "+f"(d[0]), "+f"(d[1]), "+f"(d[2]), "+f"(d[3])
        : "r"(a[0]), "r"(a[1]), "r"(a[2]), "r"(a[3]), "r"(b[0]), "r"(b[1]));
}

__global__ void __launch_bounds__(NTHR, 1)
fa_tf32_kernel(const float* __restrict__ Q, const float* __restrict__ K,
               const float* __restrict__ V, const int* __restrict__ PM,
               float* __restrict__ O)
{
    extern __shared__ uint32_t sm[];
    uint32_t* Qs = sm + QS_OFF;
    uint32_t* Ks = sm + KS_OFF;
    uint32_t* Vs = sm + VS_OFF;
    uint32_t* Ps = sm + PS_OFF;
    int* pads    = (int*)(sm + PAD_OFF);

    const int tid  = threadIdx.x;
    const int warp = tid >> 5;
    const int lane = tid & 31;
    const int g    = lane >> 2;   // group id (row within 8)
    const int t    = lane & 3;    // thread-in-group

    const int b  = blockIdx.x & (BATCH - 1);
    const int qt = NTQ - 1 - (blockIdx.x >> 4);   // heavy tiles first
    const int q0 = qt * BQ;

    // ---- stage Q tile into A-fragment layout (pre-scaled, tf32) ----
    const float* Qg = Q + ((size_t)b * SEQ + q0) * DIM;
    for (int i = tid; i < BQ * DIM / 4; i += NTHR) {
        int idx = i * 4;
        float4 v = *reinterpret_cast<const float4*>(Qg + idx);
        int r = idx >> 8;       // local q row
        int d = idx & 255;
        float vv[4] = {v.x, v.y, v.z, v.w};
        #pragma unroll
        for (int e = 0; e < 4; e++) {
            int dd = d + e;
            int wrb   = r >> 4;
            int c     = dd >> 3;
            int lane2 = ((r & 7) << 2) | (dd & 3);
            int a     = ((r >> 3) & 1) | (((dd >> 2) & 1) << 1);
            Qs[((wrb * 32 + c) * 32 + lane2) * 4 + a] = f2tf32(vv[e] * QK_SCALE);
        }
    }

    // ---- accumulators ----
    float o[32][4];
    #pragma unroll
    for (int i = 0; i < 32; i++) { o[i][0] = 0.f; o[i][1] = 0.f; o[i][2] = 0.f; o[i][3] = 0.f; }
    float m0 = -1e30f, m1 = -1e30f, l0 = 0.f, l1 = 0.f;

    const int wrow = q0 + warp * 16;        // first q row owned by this warp
    const int KT   = (q0 + BQ) / BK;        // causal: tiles 0..KT-1
    const float* Kg0 = K + (size_t)b * SEQ * DIM;
    const float* Vg0 = V + (size_t)b * SEQ * DIM;

    for (int kt = 0; kt < KT; kt++) {
        const int k0 = kt * BK;

        __syncthreads();   // previous-iteration smem reads done
        // ---- stage K,V tiles into B-fragment layouts (tf32) ----
        const float* Kg = Kg0 + (size_t)k0 * DIM;
        const float* Vg = Vg0 + (size_t)k0 * DIM;
        for (int i = tid; i < BK * DIM / 4; i += NTHR) {
            int idx = i * 4;
            float4 kv = *reinterpret_cast<const float4*>(Kg + idx);
            float4 vv = *reinterpret_cast<const float4*>(Vg + idx);
            int r = idx >> 8;      // local kv row
            int d = idx & 255;
            float ka[4] = {kv.x, kv.y, kv.z, kv.w};
            float va[4] = {vv.x, vv.y, vv.z, vv.w};
            #pragma unroll
            for (int e = 0; e < 4; e++) {
                int dd = d + e;
                // K B-frag for QK^T: [nt=kv/8][c=d/8][lane=(kv%8)*4+(d%4)][bi=(d%8)/4]
                Ks[(((r >> 3) * 32 + (dd >> 3)) * 32 + (((r & 7) << 2) | (dd & 3))) * 2
                   + ((dd >> 2) & 1)] = f2tf32(ka[e]);
                // V B-frag for P*V: [dt=d/8][kc=kv/8][lane=(d%8)*4+(kv%4)][bi=(kv%8)/4]
                Vs[(((dd >> 3) * 4 + (r >> 3)) * 32 + (((dd & 7) << 2) | (r & 3))) * 2
                   + ((r >> 2) & 1)] = f2tf32(va[e]);
            }
        }
        if (tid < BK) pads[tid] = PM[(size_t)b * SEQ + k0 + tid];
        __syncthreads();

        if (k0 > wrow + 15) continue;   // tile fully above the diagonal for this warp

        // ---- S = (Q*scale) K^T ----
        float s[4][4];
        #pragma unroll
        for (int nt = 0; nt < 4; nt++) { s[nt][0] = s[nt][1] = s[nt][2] = s[nt][3] = 0.f; }
        #pragma unroll
        for (int c = 0; c < 32; c++) {
            uint4 qa = *reinterpret_cast<const uint4*>(&Qs[((warp * 32 + c) * 32 + lane) * 4]);
            uint32_t A[4] = {qa.x, qa.y, qa.z, qa.w};
            #pragma unroll
            for (int nt = 0; nt < 4; nt++) {
                uint2 kb = *reinterpret_cast<const uint2*>(&Ks[((nt * 32 + c) * 32 + lane) * 2]);
                uint32_t Bf[2] = {kb.x, kb.y};
                mma8(s[nt], A, Bf);
            }
        }

        // ---- mask + online softmax ----
        const int row0 = wrow + g;
        const int row1 = row0 + 8;
        float rm0 = -1e30f, rm1 = -1e30f;
        #pragma unroll
        for (int nt = 0; nt < 4; nt++) {
            int j0 = k0 + nt * 8 + 2 * t;
            int j1 = j0 + 1;
            bool ok0 = (pads[j0 - k0] != 0);
            bool ok1 = (pads[j1 - k0] != 0);
            if (!(ok0 && j0 <= row0)) s[nt][0] = -1e30f;
            if (!(ok1 && j1 <= row0)) s[nt][1] = -1e30f;
            if (!(ok0 && j0 <= row1)) s[nt][2] = -1e30f;
            if (!(ok1 && j1 <= row1)) s[nt][3] = -1e30f;
            rm0 = fmaxf(rm0, fmaxf(s[nt][0], s[nt][1]));
            rm1 = fmaxf(rm1, fmaxf(s[nt][2], s[nt][3]));
        }
        rm0 = fmaxf(rm0, __shfl_xor_sync(0xffffffffu, rm0, 1));
        rm0 = fmaxf(rm0, __shfl_xor_sync(0xffffffffu, rm0, 2));
        rm1 = fmaxf(rm1, __shfl_xor_sync(0xffffffffu, rm1, 1));
        rm1 = fmaxf(rm1, __shfl_xor_sync(0xffffffffu, rm1, 2));

        float mn0 = fmaxf(m0, rm0), mn1 = fmaxf(m1, rm1);
        float sc0 = ex2((m0 - mn0) * LOG2E);
        float sc1 = ex2((m1 - mn1) * LOG2E);
        m0 = mn0; m1 = mn1;
        l0 *= sc0; l1 *= sc1;
        #pragma unroll
        for (int dt = 0; dt < 32; dt++) {
            o[dt][0] *= sc0; o[dt][1] *= sc0;
            o[dt][2] *= sc1; o[dt][3] *= sc1;
        }

        __syncwarp();   // prior PV reads of Ps done before overwrite
        float ls0 = 0.f, ls1 = 0.f;
        #pragma unroll
        for (int nt = 0; nt < 4; nt++) {
            float p0 = ex2((s[nt][0] - mn0) * LOG2E);
            float p1 = ex2((s[nt][1] - mn0) * LOG2E);
            float p2 = ex2((s[nt][2] - mn1) * LOG2E);
            float p3 = ex2((s[nt][3] - mn1) * LOG2E);
            ls0 += p0 + p1;
            ls1 += p2 + p3;
            // C-layout -> A-fragment layout (per-warp private region)
            int base = (warp * 4 + nt) * 32;
            int t20 = (2 * t) & 3,     hi0 = (2 * t) >> 2;
            int t21 = (2 * t + 1) & 3, hi1 = (2 * t + 1) >> 2;
            Ps[(base + g * 4 + t20) * 4 + 0 + 2 * hi0] = f2tf32(p0);
            Ps[(base + g * 4 + t21) * 4 + 0 + 2 * hi1] = f2tf32(p1);
            Ps[(base + g * 4 + t20) * 4 + 1 + 2 * hi0] = f2tf32(p2);
            Ps[(base + g * 4 + t21) * 4 + 1 + 2 * hi1] = f2tf32(p3);
        }
        l0 += ls0; l1 += ls1;
        __syncwarp();

        // ---- O += P V ----
        #pragma unroll
        for (int kc = 0; kc < 4; kc++) {
            uint4 pa = *reinterpret_cast<const uint4*>(&Ps[((warp * 4 + kc) * 32 + lane) * 4]);
            uint32_t A[4] = {pa.x, pa.y, pa.z, pa.w};
            #pragma unroll
            for (int dt = 0; dt < 32; dt++) {
                uint2 vb = *reinterpret_cast<const uint2*>(&Vs[((dt * 4 + kc) * 32 + lane) * 2]);
                uint32_t Bf[2] = {vb.x, vb.y};
                mma8(o[dt], A, Bf);
            }
        }
    }

    // ---- epilogue: finish l across the quad, divide, store ----
    l0 += __shfl_xor_sync(0xffffffffu, l0, 1);
    l0 += __shfl_xor_sync(0xffffffffu, l0, 2);
    l1 += __shfl_xor_sync(0xffffffffu, l1, 1);
    l1 += __shfl_xor_sync(0xffffffffu, l1, 2);
    float inv0 = 1.f / l0;
    float inv1 = 1.f / l1;

    float* Og0 = O + ((size_t)b * SEQ + wrow + g) * DIM;
    float* Og1 = Og0 + 8 * DIM;
    #pragma unroll
    for (int dt = 0; dt < 32; dt++) {
        int col = dt * 8 + 2 * t;
        float2 v0 = make_float2(o[dt][0] * inv0, o[dt][1] * inv0);
        float2 v1 = make_float2(o[dt][2] * inv1, o[dt][3] * inv1);
        *reinterpret_cast<float2*>(Og0 + col) = v0;
        *reinterpret_cast<float2*>(Og1 + col) = v1;
    }
}

extern "C" void kernel_launch(void* const* d_in, const int* in_sizes, int n_in,
                              void* d_out, int out_size)
{
    const float* Q  = (const float*)d_in[0];
    const float* K  = (const float*)d_in[1];
    const float* V  = (const float*)d_in[2];
    const int*   PM = (const int*)d_in[3];
    float*       O  = (float*)d_out;

    cudaFuncSetAttribute(fa_tf32_kernel,
                         cudaFuncAttributeMaxDynamicSharedMemorySize, SMEM_BYTES);
    fa_tf32_kernel<<<BATCH * NTQ, NTHR, SMEM_BYTES>>>(Q, K, V, PM, O);
}

// round 3
// speedup vs baseline: 1.0032x; 1.0032x over previous
#include <cuda_runtime.h>
#include <cuda_bf16.h>
#include <cstdint>

// Causal attention, B=16, N=2048, D=256, fp32 I/O.
// FlashAttention-2 style, tf32 mma.sync (m16n8k8), fragment-permuted smem layouts.

#define BQ    128              // q-tile rows per block
#define BK    32               // k-tile rows per iteration
#define NWARP 8
#define NTHR  256
#define BATCH 16
#define SEQ   2048
#define DIM   256
#define NTQ   (SEQ / BQ)       // 16 q-tiles per batch
#define QK_SCALE 0.0625f       // 1/sqrt(256)
#define LOG2E 1.4426950408889634f

// smem (uint32 words): tf32 bit patterns
//  Qs: [BQ/16=8][32 d-chunks][32 lanes][4]  = 32768
//  Ks: [BK/8=4][32 d-chunks][32 lanes][2]   =  8192
//  Vs: [DIM/8=32][BK/8=4][32 lanes][2]      =  8192
//  Ps: [8 warps][4 k-chunks][32 lanes][4]   =  4096
//  pads: 32 ints
#define QS_OFF 0
#define KS_OFF 32768
#define VS_OFF 40960
#define PS_OFF 49152
#define PAD_OFF 53248
#define SMEM_WORDS (53248 + 32)
#define SMEM_BYTES (SMEM_WORDS * 4)

__device__ __forceinline__ uint32_t f2tf32(float x) {
    uint32_t u;
    asm("cvt.rna.tf32.f32 %0, %1;" : "=r"(u) : "f"(x));
    return u;
}

__device__ __forceinline__ float ex2(float x) {
    float r;
    asm("ex2.approx.ftz.f32 %0, %1;" : "=f"(r) : "f"(x));
    return r;
}

__device__ __forceinline__ void mma8(float* d, const uint32_t* a, const uint32_t* b) {
    asm volatile(
        "mma.sync.aligned.m16n8k8.row.col.f32.tf32.tf32.f32 "
        "{%0,%1,%2,%3},{%4,%5,%6,%7},{%8,%9},{%0,%1,%2,%3};\n"
        : "+f"(d[0]), "+f"(d[1]), "+f"(d[2]), "+f"(d[3])
        : "r"(a[0]), "r"(a[1]), "r"(a[2]), "r"(a[3]), "r"(b[0]), "r"(b[1]));
}

__global__ void __launch_bounds__(NTHR, 1)
fa_tf32_kernel(const float* __restrict__ Q, const float* __restrict__ K,
               const float* __restrict__ V, const int* __restrict__ PM,
               float* __restrict__ O)
{
    extern __shared__ uint32_t sm[];
    uint32_t* Qs = sm + QS_OFF;
    uint32_t* Ks = sm + KS_OFF;
    uint32_t* Vs = sm + VS_OFF;
    uint32_t* Ps = sm + PS_OFF;
    int* pads    = (int*)(sm + PAD_OFF);

    const int tid  = threadIdx.x;
    const int warp = tid >> 5;
    const int lane = tid & 31;
    const int g    = lane >> 2;   // group id (row within 8)
    const int t    = lane & 3;    // thread-in-group

    const int b  = blockIdx.x & (BATCH - 1);
    const int qt = NTQ - 1 - (blockIdx.x >> 4);   // heavy tiles first
    const int q0 = qt * BQ;

    // ---- stage Q tile into A-fragment layout (pre-scaled, tf32) ----
    const float* Qg = Q + ((size_t)b * SEQ + q0) * DIM;
    for (int i = tid; i < BQ * DIM / 4; i += NTHR) {
        int idx = i * 4;
        float4 v = *reinterpret_cast<const float4*>(Qg + idx);
        int r = idx >> 8;       // local q row
        int d = idx & 255;
        float vv[4] = {v.x, v.y, v.z, v.w};
        #pragma unroll
        for (int e = 0; e < 4; e++) {
            int dd = d + e;
            int wrb   = r >> 4;
            int c     = dd >> 3;
            int lane2 = ((r & 7) << 2) | (dd & 3);
            int a     = ((r >> 3) & 1) | (((dd >> 2) & 1) << 1);
            Qs[((wrb * 32 + c) * 32 + lane2) * 4 + a] = f2tf32(vv[e] * QK_SCALE);
        }
    }

    // ---- accumulators ----
    float o[32][4];
    #pragma unroll
    for (int i = 0; i < 32; i++) { o[i][0] = 0.f; o[i][1] = 0.f; o[i][2] = 0.f; o[i][3] = 0.f; }
    float m0 = -1e30f, m1 = -1e30f, l0 = 0.f, l1 = 0.f;

    const int wrow = q0 + warp * 16;        // first q row owned by this warp
    const int KT   = (q0 + BQ) / BK;        // causal: tiles 0..KT-1
    const float* Kg0 = K + (size_t)b * SEQ * DIM;
    const float* Vg0 = V + (size_t)b * SEQ * DIM;

    for (int kt = 0; kt < KT; kt++) {
        const int k0 = kt * BK;

        __syncthreads();   // previous-iteration smem reads done
        // ---- stage K,V tiles into B-fragment layouts (tf32) ----
        const float* Kg = Kg0 + (size_t)k0 * DIM;
        const float* Vg = Vg0 + (size_t)k0 * DIM;
        for (int i = tid; i < BK * DIM / 4; i += NTHR) {
            int idx = i * 4;
            float4 kv = *reinterpret_cast<const float4*>(Kg + idx);
            float4 vv = *reinterpret_cast<const float4*>(Vg + idx);
            int r = idx >> 8;      // local kv row
            int d = idx & 255;
            float ka[4] = {kv.x, kv.y, kv.z, kv.w};
            float va[4] = {vv.x, vv.y, vv.z, vv.w};
            #pragma unroll
            for (int e = 0; e < 4; e++) {
                int dd = d + e;
                // K B-frag for QK^T: [nt=kv/8][c=d/8][lane=(kv%8)*4+(d%4)][bi=(d%8)/4]
                Ks[(((r >> 3) * 32 + (dd >> 3)) * 32 + (((r & 7) << 2) | (dd & 3))) * 2
                   + ((dd >> 2) & 1)] = f2tf32(ka[e]);
                // V B-frag for P*V: [dt=d/8][kc=kv/8][lane=(d%8)*4+(kv%4)][bi=(kv%8)/4]
                Vs[(((dd >> 3) * 4 + (r >> 3)) * 32 + (((dd & 7) << 2) | (r & 3))) * 2
                   + ((r >> 2) & 1)] = f2tf32(va[e]);
            }
        }
        if (tid < BK) pads[tid] = PM[(size_t)b * SEQ + k0 + tid];
        __syncthreads();

        if (k0 > wrow + 15) continue;   // tile fully above the diagonal for this warp

        // ---- S = (Q*scale) K^T ----
        float s[4][4];
        #pragma unroll
        for (int nt = 0; nt < 4; nt++) { s[nt][0] = s[nt][1] = s[nt][2] = s[nt][3] = 0.f; }
        #pragma unroll
        for (int c = 0; c < 32; c++) {
            uint4 qa = *reinterpret_cast<const uint4*>(&Qs[((warp * 32 + c) * 32 + lane) * 4]);
            uint32_t A[4] = {qa.x, qa.y, qa.z, qa.w};
            #pragma unroll
            for (int nt = 0; nt < 4; nt++) {
                uint2 kb = *reinterpret_cast<const uint2*>(&Ks[((nt * 32 + c) * 32 + lane) * 2]);
                uint32_t Bf[2] = {kb.x, kb.y};
                mma8(s[nt], A, Bf);
            }
        }

        // ---- mask + online softmax ----
        const int row0 = wrow + g;
        const int row1 = row0 + 8;
        float rm0 = -1e30f, rm1 = -1e30f;
        #pragma unroll
        for (int nt = 0; nt < 4; nt++) {
            int j0 = k0 + nt * 8 + 2 * t;
            int j1 = j0 + 1;
            bool ok0 = (pads[j0 - k0] != 0);
            bool ok1 = (pads[j1 - k0] != 0);
            if (!(ok0 && j0 <= row0)) s[nt][0] = -1e30f;
            if (!(ok1 && j1 <= row0)) s[nt][1] = -1e30f;
            if (!(ok0 && j0 <= row1)) s[nt][2] = -1e30f;
            if (!(ok1 && j1 <= row1)) s[nt][3] = -1e30f;
            rm0 = fmaxf(rm0, fmaxf(s[nt][0], s[nt][1]));
            rm1 = fmaxf(rm1, fmaxf(s[nt][2], s[nt][3]));
        }
        rm0 = fmaxf(rm0, __shfl_xor_sync(0xffffffffu, rm0, 1));
        rm0 = fmaxf(rm0, __shfl_xor_sync(0xffffffffu, rm0, 2));
        rm1 = fmaxf(rm1, __shfl_xor_sync(0xffffffffu, rm1, 1));
        rm1 = fmaxf(rm1, __shfl_xor_sync(0xffffffffu, rm1, 2));

        float mn0 = fmaxf(m0, rm0), mn1 = fmaxf(m1, rm1);
        float sc0 = ex2((m0 - mn0) * LOG2E);
        float sc1 = ex2((m1 - mn1) * LOG2E);
        m0 = mn0; m1 = mn1;
        l0 *= sc0; l1 *= sc1;
        #pragma unroll
        for (int dt = 0; dt < 32; dt++) {
            o[dt][0] *= sc0; o[dt][1] *= sc0;
            o[dt][2] *= sc1; o[dt][3] *= sc1;
        }

        __syncwarp();   // prior PV reads of Ps done before overwrite
        float ls0 = 0.f, ls1 = 0.f;
        #pragma unroll
        for (int nt = 0; nt < 4; nt++) {
            float p0 = ex2((s[nt][0] - mn0) * LOG2E);
            float p1 = ex2((s[nt][1] - mn0) * LOG2E);
            float p2 = ex2((s[nt][2] - mn1) * LOG2E);
            float p3 = ex2((s[nt][3] - mn1) * LOG2E);
            ls0 += p0 + p1;
            ls1 += p2 + p3;
            // C-layout -> A-fragment layout (per-warp private region)
            int base = (warp * 4 + nt) * 32;
            int t20 = (2 * t) & 3,     hi0 = (2 * t) >> 2;
            int t21 = (2 * t + 1) & 3, hi1 = (2 * t + 1) >> 2;
            Ps[(base + g * 4 + t20) * 4 + 0 + 2 * hi0] = f2tf32(p0);
            Ps[(base + g * 4 + t21) * 4 + 0 + 2 * hi1] = f2tf32(p1);
            Ps[(base + g * 4 + t20) * 4 + 1 + 2 * hi0] = f2tf32(p2);
            Ps[(base + g * 4 + t21) * 4 + 1 + 2 * hi1] = f2tf32(p3);
        }
        l0 += ls0; l1 += ls1;
        __syncwarp();

        // ---- O += P V ----
        #pragma unroll
        for (int kc = 0; kc < 4; kc++) {
            uint4 pa = *reinterpret_cast<const uint4*>(&Ps[((warp * 4 + kc) * 32 + lane) * 4]);
            uint32_t A[4] = {pa.x, pa.y, pa.z, pa.w};
            #pragma unroll
            for (int dt = 0; dt < 32; dt++) {
                uint2 vb = *reinterpret_cast<const uint2*>(&Vs[((dt * 4 + kc) * 32 + lane) * 2]);
                uint32_t Bf[2] = {vb.x, vb.y};
                mma8(o[dt], A, Bf);
            }
        }
    }

    // ---- epilogue: finish l across the quad, divide, store ----
    l0 += __shfl_xor_sync(0xffffffffu, l0, 1);
    l0 += __shfl_xor_sync(0xffffffffu, l0, 2);
    l1 += __shfl_xor_sync(0xffffffffu, l1, 1);
    l1 += __shfl_xor_sync(0xffffffffu, l1, 2);
    float inv0 = 1.f / l0;
    float inv1 = 1.f / l1;

    float* Og0 = O + ((size_t)b * SEQ + wrow + g) * DIM;
    float* Og1 = Og0 + 8 * DIM;
    #pragma unroll
    for (int dt = 0; dt < 32; dt++) {
        int col = dt * 8 + 2 * t;
        float2 v0 = make_float2(o[dt][0] * inv0, o[dt][1] * inv0);
        float2 v1 = make_float2(o[dt][2] * inv1, o[dt][3] * inv1);
        *reinterpret_cast<float2*>(Og0 + col) = v0;
        *reinterpret_cast<float2*>(Og1 + col) = v1;
    }
}

extern "C" void kernel_launch(void* const* d_in, const int* in_sizes, int n_in,
                              void* d_out, int out_size)
{
    const float* Q  = (const float*)d_in[0];
    const float* K  = (const float*)d_in[1];
    const float* V  = (const float*)d_in[2];
    const int*   PM = (const int*)d_in[3];
    float*       O  = (float*)d_out;

    cudaFuncSetAttribute(fa_tf32_kernel,
                         cudaFuncAttributeMaxDynamicSharedMemorySize, SMEM_BYTES);
    fa_tf32_kernel<<<BATCH * NTQ, NTHR, SMEM_BYTES>>>(Q, K, V, PM, O);
}

// round 6
// speedup vs baseline: 1.5356x; 1.5308x over previous
#include <cuda_runtime.h>
#include <cuda_bf16.h>
#include <cstdint>

// Causal attention, B=16, N=2048, D=256, fp32 I/O.
// FlashAttention-2 style, tf32 mma.sync (m16n8k8), fragment-permuted smem layouts.
// R5: XOR bank-swizzle on Q/K/V fragment layouts -> staging stores 16-way -> 2-way.

#define BQ    128
#define BK    32
#define NWARP 8
#define NTHR  256
#define BATCH 16
#define SEQ   2048
#define DIM   256
#define NTQ   (SEQ / BQ)
#define QK_SCALE 0.0625f
#define LOG2E 1.4426950408889634f

// smem (uint32 words)
#define QS_OFF 0        // Q A-frags: 8 wrb * 32 c * 128 words
#define KS_OFF 32768    // K B-frags: 4 nt * 32 c * 64 words
#define VS_OFF 40960    // V B-frags: 32 dt * 4 kc * 64 words
#define PS_OFF 49152    // P A-frags: 8 warp * 4 nt * 128 words
#define PAD_OFF 53248
#define SMEM_WORDS (53248 + 32)
#define SMEM_BYTES (SMEM_WORDS * 4)

__device__ __forceinline__ uint32_t f2tf32(float x) {
    uint32_t u;
    asm("cvt.rna.tf32.f32 %0, %1;" : "=r"(u) : "f"(x));
    return u;
}

__device__ __forceinline__ float ex2(float x) {
    float r;
    asm("ex2.approx.ftz.f32 %0, %1;" : "=f"(r) : "f"(x));
    return r;
}

__device__ __forceinline__ void mma8(float* d, const uint32_t* a, const uint32_t* b) {
    asm volatile(
        "mma.sync.aligned.m16n8k8.row.col.f32.tf32.tf32.f32 "
        "{%0,%1,%2,%3},{%4,%5,%6,%7},{%8,%9},{%0,%1,%2,%3};\n"
        : "+f"(d[0]), "+f"(d[1]), "+f"(d[2]), "+f"(d[3])
        : "r"(a[0]), "r"(a[1]), "r"(a[2]), "r"(a[3]), "r"(b[0]), "r"(b[1]));
}

__global__ void __launch_bounds__(NTHR, 1)
fa_tf32_kernel(const float* __restrict__ Q, const float* __restrict__ K,
               const float* __restrict__ V, const int* __restrict__ PM,
               float* __restrict__ O)
{
    extern __shared__ uint32_t sm[];
    uint32_t* Qs = sm + QS_OFF;
    uint32_t* Ks = sm + KS_OFF;
    uint32_t* Vs = sm + VS_OFF;
    uint32_t* Ps = sm + PS_OFF;
    int* pads    = (int*)(sm + PAD_OFF);

    const int tid  = threadIdx.x;
    const int warp = tid >> 5;
    const int lane = tid & 31;
    const int g    = lane >> 2;
    const int t    = lane & 3;

    const int b  = blockIdx.x & (BATCH - 1);
    const int qt = NTQ - 1 - (blockIdx.x >> 4);
    const int q0 = qt * BQ;

    // ---- stage Q tile into A-fragment layout (pre-scaled, tf32, XOR-swizzled) ----
    const float* Qg = Q + ((size_t)b * SEQ + q0) * DIM;
    for (int i = tid; i < BQ * DIM / 4; i += NTHR) {
        int idx = i * 4;
        float4 v = *reinterpret_cast<const float4*>(Qg + idx);
        int r = idx >> 8;
        int d = idx & 255;
        float vv[4] = {v.x, v.y, v.z, v.w};
        #pragma unroll
        for (int e = 0; e < 4; e++) {
            int dd = d + e;
            int wrb   = r >> 4;
            int c     = dd >> 3;
            int lane2 = ((r & 7) << 2) | (dd & 3);
            int a     = ((r >> 3) & 1) | (((dd >> 2) & 1) << 1);
            uint32_t off = (uint32_t)(((lane2 << 2) | a) ^ ((c & 7) << 2));
            Qs[(uint32_t)(wrb * 32 + c) * 128 + off] = f2tf32(vv[e] * QK_SCALE);
        }
    }

    // ---- accumulators ----
    float o[32][4];
    #pragma unroll
    for (int i = 0; i < 32; i++) { o[i][0] = 0.f; o[i][1] = 0.f; o[i][2] = 0.f; o[i][3] = 0.f; }
    float m0 = -1e30f, m1 = -1e30f, l0 = 0.f, l1 = 0.f;

    const int wrow = q0 + warp * 16;
    const int KT   = (q0 + BQ) / BK;
    const float* Kg0 = K + (size_t)b * SEQ * DIM;
    const float* Vg0 = V + (size_t)b * SEQ * DIM;

    for (int kt = 0; kt < KT; kt++) {
        const int k0 = kt * BK;

        __syncthreads();
        // ---- stage K,V tiles into XOR-swizzled B-fragment layouts ----
        const float* Kg = Kg0 + (size_t)k0 * DIM;
        const float* Vg = Vg0 + (size_t)k0 * DIM;
        for (int i = tid; i < BK * DIM / 4; i += NTHR) {
            int idx = i * 4;
            float4 kv = *reinterpret_cast<const float4*>(Kg + idx);
            float4 vv = *reinterpret_cast<const float4*>(Vg + idx);
            int r = idx >> 8;
            int d = idx & 255;
            float ka[4] = {kv.x, kv.y, kv.z, kv.w};
            float va[4] = {vv.x, vv.y, vv.z, vv.w};
            #pragma unroll
            for (int e = 0; e < 4; e++) {
                int dd = d + e;
                // K: block (nt=r/8, c=dd/8) of 64 words; off = lane2*2+bi ^ swz(c)
                {
                    int nt    = r >> 3;
                    int c     = dd >> 3;
                    int lane2 = ((r & 7) << 2) | (dd & 3);
                    int bi    = (dd >> 2) & 1;
                    uint32_t off = (uint32_t)(((lane2 << 1) | bi) ^ ((c & 15) << 1));
                    Ks[(uint32_t)(nt * 32 + c) * 64 + off] = f2tf32(ka[e]);
                }
                // V: block (dt=dd/8, kc=r/8) of 64 words; off = lane2*2+bi ^ swz(dt)
                {
                    int dt    = dd >> 3;
                    int kc    = r >> 3;
                    int lane2 = ((dd & 7) << 2) | (r & 3);
                    int bi    = (r >> 2) & 1;
                    uint32_t off = (uint32_t)(((lane2 << 1) | bi) ^ ((dt & 15) << 1));
                    Vs[(uint32_t)(dt * 4 + kc) * 64 + off] = f2tf32(va[e]);
                }
            }
        }
        if (tid < BK) pads[tid] = PM[(size_t)b * SEQ + k0 + tid];
        __syncthreads();

        if (k0 > wrow + 15) continue;

        // ---- S = (Q*scale) K^T ----
        float s[4][4];
        #pragma unroll
        for (int nt = 0; nt < 4; nt++) { s[nt][0] = s[nt][1] = s[nt][2] = s[nt][3] = 0.f; }
        #pragma unroll
        for (int c = 0; c < 32; c++) {
            uint32_t qoff = (uint32_t)((lane << 2) ^ ((c & 7) << 2));
            uint4 qa = *reinterpret_cast<const uint4*>(&Qs[(uint32_t)(warp * 32 + c) * 128 + qoff]);
            uint32_t A[4] = {qa.x, qa.y, qa.z, qa.w};
            uint32_t koff = (uint32_t)((lane << 1) ^ ((c & 15) << 1));
            #pragma unroll
            for (int nt = 0; nt < 4; nt++) {
                uint2 kb = *reinterpret_cast<const uint2*>(&Ks[(uint32_t)(nt * 32 + c) * 64 + koff]);
                uint32_t Bf[2] = {kb.x, kb.y};
                mma8(s[nt], A, Bf);
            }
        }

        // ---- mask + online softmax ----
        const int row0 = wrow + g;
        const int row1 = row0 + 8;
        float rm0 = -1e30f, rm1 = -1e30f;
        #pragma unroll
        for (int nt = 0; nt < 4; nt++) {
            int j0 = k0 + nt * 8 + 2 * t;
            int j1 = j0 + 1;
            bool ok0 = (pads[j0 - k0] != 0);
            bool ok1 = (pads[j1 - k0] != 0);
            if (!(ok0 && j0 <= row0)) s[nt][0] = -1e30f;
            if (!(ok1 && j1 <= row0)) s[nt][1] = -1e30f;
            if (!(ok0 && j0 <= row1)) s[nt][2] = -1e30f;
            if (!(ok1 && j1 <= row1)) s[nt][3] = -1e30f;
            rm0 = fmaxf(rm0, fmaxf(s[nt][0], s[nt][1]));
            rm1 = fmaxf(rm1, fmaxf(s[nt][2], s[nt][3]));
        }
        rm0 = fmaxf(rm0, __shfl_xor_sync(0xffffffffu, rm0, 1));
        rm0 = fmaxf(rm0, __shfl_xor_sync(0xffffffffu, rm0, 2));
        rm1 = fmaxf(rm1, __shfl_xor_sync(0xffffffffu, rm1, 1));
        rm1 = fmaxf(rm1, __shfl_xor_sync(0xffffffffu, rm1, 2));

        float mn0 = fmaxf(m0, rm0), mn1 = fmaxf(m1, rm1);
        float sc0 = ex2((m0 - mn0) * LOG2E);
        float sc1 = ex2((m1 - mn1) * LOG2E);
        m0 = mn0; m1 = mn1;
        l0 *= sc0; l1 *= sc1;
        #pragma unroll
        for (int dt = 0; dt < 32; dt++) {
            o[dt][0] *= sc0; o[dt][1] *= sc0;
            o[dt][2] *= sc1; o[dt][3] *= sc1;
        }

        __syncwarp();
        float ls0 = 0.f, ls1 = 0.f;
        #pragma unroll
        for (int nt = 0; nt < 4; nt++) {
            float p0 = ex2((s[nt][0] - mn0) * LOG2E);
            float p1 = ex2((s[nt][1] - mn0) * LOG2E);
            float p2 = ex2((s[nt][2] - mn1) * LOG2E);
            float p3 = ex2((s[nt][3] - mn1) * LOG2E);
            ls0 += p0 + p1;
            ls1 += p2 + p3;
            int base = (warp * 4 + nt) * 128;
            int t20 = (2 * t) & 3,     hi0 = (2 * t) >> 2;
            int t21 = (2 * t + 1) & 3, hi1 = (2 * t + 1) >> 2;
            Ps[base + (g * 4 + t20) * 4 + 0 + 2 * hi0] = f2tf32(p0);
            Ps[base + (g * 4 + t21) * 4 + 0 + 2 * hi1] = f2tf32(p1);
            Ps[base + (g * 4 + t20) * 4 + 1 + 2 * hi0] = f2tf32(p2);
            Ps[base + (g * 4 + t21) * 4 + 1 + 2 * hi1] = f2tf32(p3);
        }
        l0 += ls0; l1 += ls1;
        __syncwarp();

        // ---- O += P V ----
        #pragma unroll
        for (int kc = 0; kc < 4; kc++) {
            uint4 pa = *reinterpret_cast<const uint4*>(&Ps[(warp * 4 + kc) * 128 + lane * 4]);
            uint32_t A[4] = {pa.x, pa.y, pa.z, pa.w};
            #pragma unroll
            for (int dt = 0; dt < 32; dt++) {
                uint32_t voff = (uint32_t)((lane << 1) ^ ((dt & 15) << 1));
                uint2 vb = *reinterpret_cast<const uint2*>(&Vs[(uint32_t)(dt * 4 + kc) * 64 + voff]);
                uint32_t Bf[2] = {vb.x, vb.y};
                mma8(o[dt], A, Bf);
            }
        }
    }

    // ---- epilogue ----
    l0 += __shfl_xor_sync(0xffffffffu, l0, 1);
    l0 += __shfl_xor_sync(0xffffffffu, l0, 2);
    l1 += __shfl_xor_sync(0xffffffffu, l1, 1);
    l1 += __shfl_xor_sync(0xffffffffu, l1, 2);
    float inv0 = 1.f / l0;
    float inv1 = 1.f / l1;

    float* Og0 = O + ((size_t)b * SEQ + wrow + g) * DIM;
    float* Og1 = Og0 + 8 * DIM;
    #pragma unroll
    for (int dt = 0; dt < 32; dt++) {
        int col = dt * 8 + 2 * t;
        float2 v0 = make_float2(o[dt][0] * inv0, o[dt][1] * inv0);
        float2 v1 = make_float2(o[dt][2] * inv1, o[dt][3] * inv1);
        *reinterpret_cast<float2*>(Og0 + col) = v0;
        *reinterpret_cast<float2*>(Og1 + col) = v1;
    }
}

extern "C" void kernel_launch(void* const* d_in, const int* in_sizes, int n_in,
                              void* d_out, int out_size)
{
    const float* Q  = (const float*)d_in[0];
    const float* K  = (const float*)d_in[1];
    const float* V  = (const float*)d_in[2];
    const int*   PM = (const int*)d_in[3];
    float*       O  = (float*)d_out;

    cudaFuncSetAttribute(fa_tf32_kernel,
                         cudaFuncAttributeMaxDynamicSharedMemorySize, SMEM_BYTES);
    fa_tf32_kernel<<<BATCH * NTQ, NTHR, SMEM_BYTES>>>(Q, K, V, PM, O);
}